// round 2
// baseline (speedup 1.0000x reference)
#include <cuda_runtime.h>
#include <math.h>

#define NN 50000
#define NE 800000
#define AD 128
#define SD 64
#define NL 4

// ---------------- scratch (static device globals; no allocation) ----------------
__device__ float d_h2[NN * AD];
__device__ float d_agg[NN * AD];
__device__ float d_hbuf[NN * AD];
__device__ float d_t[NN * SD];
__device__ float d_msg[NN * SD];
__device__ float d_gbuf[NN * SD];
__device__ float d_alpha[NE];
__device__ float d_amax[NN];
__device__ float d_denom[NN];
__device__ float d_dinv[NN];
__device__ float d_dinv2[NN];
__device__ int   d_deg[NN];

__device__ __forceinline__ float gelu_exact(float x) {
    return 0.5f * x * (1.0f + erff(x * 0.7071067811865476f));
}

// ---------------- degree / normalization ----------------
__global__ void k_deg_count(const int* __restrict__ ei) {
    int e = blockIdx.x * blockDim.x + threadIdx.x;
    if (e < NE) atomicAdd(&d_deg[ei[NE + e]], 1);
}

__global__ void k_dinv() {
    int n = blockIdx.x * blockDim.x + threadIdx.x;
    if (n < NN) {
        float dg = (float)(d_deg[n] + 1);   // +1 self loop
        float r = rsqrtf(dg);
        d_dinv[n] = r;
        d_dinv2[n] = r * r;
    }
}

// ---------------- GCN: h2 = A @ W ; agg initialized with self-loop term ----------------
__global__ void k_gemm128(const float* __restrict__ A, const float* __restrict__ W) {
    __shared__ float sA[16][128];
    int j = threadIdx.x;
    int r0 = blockIdx.x * 16;
    #pragma unroll
    for (int rr = 0; rr < 16; rr++) sA[rr][j] = A[(r0 + rr) * AD + j];
    __syncthreads();

    float acc[16];
    #pragma unroll
    for (int rr = 0; rr < 16; rr++) acc[rr] = 0.f;

    for (int k = 0; k < 128; k += 4) {
        float w0 = W[(k + 0) * AD + j];
        float w1 = W[(k + 1) * AD + j];
        float w2 = W[(k + 2) * AD + j];
        float w3 = W[(k + 3) * AD + j];
        #pragma unroll
        for (int rr = 0; rr < 16; rr++) {
            float4 a4 = *reinterpret_cast<const float4*>(&sA[rr][k]);
            acc[rr] += a4.x * w0 + a4.y * w1 + a4.z * w2 + a4.w * w3;
        }
    }
    #pragma unroll
    for (int rr = 0; rr < 16; rr++) {
        int row = r0 + rr;
        float v = acc[rr];
        d_h2[row * AD + j] = v;
        d_agg[row * AD + j] = d_dinv2[row] * v;   // self-loop contribution
    }
}

// warp per edge: agg[dst] += dinv[src]*dinv[dst] * h2[src]
__global__ void k_gcn_scatter(const int* __restrict__ ei) {
    int gid = blockIdx.x * blockDim.x + threadIdx.x;
    int e = gid >> 5;
    if (e >= NE) return;
    int lane = gid & 31;
    int src = 0, dst = 0;
    float nrm = 0.f;
    if (lane == 0) {
        src = ei[e];
        dst = ei[NE + e];
        nrm = d_dinv[src] * d_dinv[dst];
    }
    src = __shfl_sync(0xffffffffu, src, 0);
    dst = __shfl_sync(0xffffffffu, dst, 0);
    nrm = __shfl_sync(0xffffffffu, nrm, 0);

    float4 v = *reinterpret_cast<const float4*>(&d_h2[src * AD + lane * 4]);
    float4 w = make_float4(nrm * v.x, nrm * v.y, nrm * v.z, nrm * v.w);
    atomicAdd(reinterpret_cast<float4*>(&d_agg[dst * AD + lane * 4]), w);
}

__global__ void k_gcn_finish(const float* __restrict__ bias, float* __restrict__ out, int apply_gelu) {
    int idx = blockIdx.x * blockDim.x + threadIdx.x;
    if (idx < NN * AD) {
        float v = d_agg[idx] + bias[idx & (AD - 1)];
        if (apply_gelu) v = gelu_exact(v);
        out[idx] = v;
    }
}

// ---------------- GNA GEMM 64x64 (smem W) ; mode 1 = final epilogue ----------------
__global__ void k_gemm64(const float* __restrict__ A, const float* __restrict__ W,
                         const float* __restrict__ bias, float* __restrict__ out,
                         int final_mode) {
    __shared__ float sW[64 * 64];
    __shared__ float sA[32 * 64];
    int tid = threadIdx.x;
    int r0 = blockIdx.x * 32;
    for (int idx = tid; idx < 4096; idx += 256) sW[idx] = W[idx];
    for (int idx = tid; idx < 2048; idx += 256) {
        int row = r0 + (idx >> 6);
        sA[idx] = (row < NN) ? A[row * SD + (idx & 63)] : 0.f;
    }
    __syncthreads();

    int j = tid & 63;
    int rg = tid >> 6;   // 0..3, 8 rows each
    float acc[8];
    #pragma unroll
    for (int rr = 0; rr < 8; rr++) acc[rr] = 0.f;

    for (int k = 0; k < 64; k += 4) {
        float w0 = sW[(k + 0) * 64 + j];
        float w1 = sW[(k + 1) * 64 + j];
        float w2 = sW[(k + 2) * 64 + j];
        float w3 = sW[(k + 3) * 64 + j];
        #pragma unroll
        for (int rr = 0; rr < 8; rr++) {
            float4 a4 = *reinterpret_cast<const float4*>(&sA[(rg * 8 + rr) * 64 + k]);
            acc[rr] += a4.x * w0 + a4.y * w1 + a4.z * w2 + a4.w * w3;
        }
    }
    #pragma unroll
    for (int rr = 0; rr < 8; rr++) {
        int row = r0 + rg * 8 + rr;
        if (row < NN) {
            float v = acc[rr] + bias[j];
            if (final_mode) {
                v += d_msg[row * SD + j] / (d_denom[row] + 1e-16f);
                v = gelu_exact(v);
            }
            out[row * SD + j] = v;
        }
    }
}

// warp per edge: alpha[e] = (t[dst]-t[src]) . a ; amax[dst] = max (>=0, self-loop alpha=0)
__global__ void k_alpha(const int* __restrict__ ei, const float* __restrict__ avec) {
    int gid = blockIdx.x * blockDim.x + threadIdx.x;
    int e = gid >> 5;
    if (e >= NE) return;
    int lane = gid & 31;
    int src = 0, dst = 0;
    if (lane == 0) {
        src = ei[e];
        dst = ei[NE + e];
    }
    src = __shfl_sync(0xffffffffu, src, 0);
    dst = __shfl_sync(0xffffffffu, dst, 0);

    float2 tc = *reinterpret_cast<const float2*>(&d_t[dst * SD + lane * 2]);
    float2 tr = *reinterpret_cast<const float2*>(&d_t[src * SD + lane * 2]);
    float2 av = *reinterpret_cast<const float2*>(&avec[lane * 2]);
    float p = (tc.x - tr.x) * av.x + (tc.y - tr.y) * av.y;
    #pragma unroll
    for (int o = 16; o > 0; o >>= 1) p += __shfl_xor_sync(0xffffffffu, p, o);

    if (lane == 0) {
        d_alpha[e] = p;
        // amax starts at 0 (self-loop); nonneg float bits are int-monotone
        if (p > 0.f) atomicMax(reinterpret_cast<int*>(&d_amax[dst]), __float_as_int(p));
    }
}

// node-wise init with the self-loop term: denom = exp(-amax), msg = exp(-amax)*t
__global__ void k_gna_init() {
    int idx = blockIdx.x * blockDim.x + threadIdx.x;
    if (idx < NN * SD) {
        int n = idx >> 6;
        float es = expf(-d_amax[n]);
        d_msg[idx] = es * d_t[idx];
        if ((idx & 63) == 0) d_denom[n] = es;
    }
}

// warp per edge: e = exp(alpha - amax[dst]); denom[dst]+=e; msg[dst]+=e*t[src]
__global__ void k_gna_scatter(const int* __restrict__ ei) {
    int gid = blockIdx.x * blockDim.x + threadIdx.x;
    int e = gid >> 5;
    if (e >= NE) return;
    int lane = gid & 31;
    int src = 0, dst = 0;
    float ew = 0.f;
    if (lane == 0) {
        src = ei[e];
        dst = ei[NE + e];
        ew = expf(d_alpha[e] - d_amax[dst]);
        atomicAdd(&d_denom[dst], ew);
    }
    src = __shfl_sync(0xffffffffu, src, 0);
    dst = __shfl_sync(0xffffffffu, dst, 0);
    ew  = __shfl_sync(0xffffffffu, ew, 0);

    float2 tr = *reinterpret_cast<const float2*>(&d_t[src * SD + lane * 2]);
    atomicAdd(reinterpret_cast<float2*>(&d_msg[dst * SD + lane * 2]),
              make_float2(ew * tr.x, ew * tr.y));
}

// ---------------- host launcher ----------------
extern "C" void kernel_launch(void* const* d_in, const int* in_sizes, int n_in,
                              void* d_out, int out_size) {
    const float* x     = (const float*)d_in[0];
    const float* s     = (const float*)d_in[1];
    const int*   ei    = (const int*)d_in[2];     // int32! (JAX x64 disabled)
    const float* gcnW  = (const float*)d_in[3];
    const float* gcnb  = (const float*)d_in[4];
    const float* w1W   = (const float*)d_in[5];
    const float* w1b   = (const float*)d_in[6];
    const float* w2W   = (const float*)d_in[7];
    const float* w2b   = (const float*)d_in[8];
    const float* ga    = (const float*)d_in[9];
    float* out = (float*)d_out;

    void* p;
    cudaGetSymbolAddress(&p, d_deg);   int*   degp  = (int*)p;
    cudaGetSymbolAddress(&p, d_amax);  float* amaxp = (float*)p;
    cudaGetSymbolAddress(&p, d_hbuf);  float* hbufp = (float*)p;
    cudaGetSymbolAddress(&p, d_gbuf);  float* gbufp = (float*)p;
    cudaGetSymbolAddress(&p, d_t);     float* tp    = (float*)p;

    const int EWB = (NE * 32) / 256;   // warp per edge

    // ---- degree / dinv ----
    cudaMemsetAsync(degp, 0, NN * sizeof(int));
    k_deg_count<<<(NE + 255) / 256, 256>>>(ei);
    k_dinv<<<(NN + 255) / 256, 256>>>();

    // ---- GCN stack ----
    const float* hin = x;
    for (int i = 0; i < NL; i++) {
        k_gemm128<<<NN / 16, 128>>>(hin, gcnW + i * AD * AD);
        k_gcn_scatter<<<EWB, 256>>>(ei);
        float* hout = (i == NL - 1) ? out : hbufp;
        k_gcn_finish<<<(NN * AD) / 256, 256>>>(gcnb + i * AD, hout, (i < NL - 1) ? 1 : 0);
        hin = hbufp;
    }

    // ---- GNA stack ----
    const float* gin = s;
    for (int i = 0; i < NL; i++) {
        k_gemm64<<<(NN + 31) / 32, 256>>>(gin, w2W + i * SD * SD, w2b + i * SD, tp, 0);
        cudaMemsetAsync(amaxp, 0, NN * sizeof(float));
        k_alpha<<<EWB, 256>>>(ei, ga + i * SD);
        k_gna_init<<<(NN * SD) / 256, 256>>>();
        k_gna_scatter<<<EWB, 256>>>(ei);
        float* gout = (i == NL - 1) ? (out + NN * AD) : gbufp;
        k_gemm64<<<(NN + 31) / 32, 256>>>(gin, w1W + i * SD * SD, w1b + i * SD, gout, 1);
        gin = gbufp;
    }
}

// round 3
// speedup vs baseline: 2.4537x; 2.4537x over previous
#include <cuda_runtime.h>
#include <math.h>

#define NN 50000
#define NE 800000
#define AD 128
#define SD 64
#define NL 4

// ---------------- scratch (static device globals; no allocation) ----------------
__device__ float d_h2[NN * AD];     // GCN post-GEMM features
__device__ float d_hbuf[NN * AD];   // GCN inter-layer buffer
__device__ float d_t[NN * SD];      // GNA w2 output
__device__ float d_msg[NN * SD];    // GNA normalized attention message
__device__ float d_gbuf[NN * SD];   // GNA inter-layer buffer
__device__ float d_proj[NN];        // t . a
__device__ float d_dinv[NN];
__device__ int   d_deg[NN];
__device__ int   d_off[NN + 1];     // CSR offsets (dst-sorted)
__device__ int   d_cur[NN];
__device__ int   d_csrc[NE];        // CSR src per position

__device__ __forceinline__ float gelu_exact(float x) {
    return 0.5f * x * (1.0f + erff(x * 0.7071067811865476f));
}

// ---------------- degree / CSR build ----------------
__global__ void k_deg_count(const int* __restrict__ ei) {
    int e = blockIdx.x * blockDim.x + threadIdx.x;
    if (e < NE) atomicAdd(&d_deg[ei[NE + e]], 1);
}

__global__ void k_dinv() {
    int n = blockIdx.x * blockDim.x + threadIdx.x;
    if (n < NN) d_dinv[n] = rsqrtf((float)(d_deg[n] + 1));
}

// single-block exclusive scan of d_deg into d_off (1024 threads)
__global__ void k_scan() {
    __shared__ int warpsums[32];
    int tid = threadIdx.x, lane = tid & 31, wid = tid >> 5;
    int carry = 0;
    if (tid == 0) d_off[0] = 0;
    for (int base = 0; base < NN; base += 1024) {
        int idx = base + tid;
        int v = (idx < NN) ? d_deg[idx] : 0;
        int x = v;
        #pragma unroll
        for (int o = 1; o < 32; o <<= 1) {
            int y = __shfl_up_sync(0xffffffffu, x, o);
            if (lane >= o) x += y;
        }
        if (lane == 31) warpsums[wid] = x;
        __syncthreads();
        if (wid == 0) {
            int w = warpsums[lane];
            #pragma unroll
            for (int o = 1; o < 32; o <<= 1) {
                int y = __shfl_up_sync(0xffffffffu, w, o);
                if (lane >= o) w += y;
            }
            warpsums[lane] = w;
        }
        __syncthreads();
        int prev = (wid > 0) ? warpsums[wid - 1] : 0;
        if (idx < NN) d_off[idx + 1] = carry + prev + x;
        int total = warpsums[31];
        __syncthreads();
        carry += total;
    }
}

__global__ void k_csr_scatter(const int* __restrict__ ei) {
    int e = blockIdx.x * blockDim.x + threadIdx.x;
    if (e < NE) {
        int src = ei[e], dst = ei[NE + e];
        int pos = atomicAdd(&d_cur[dst], 1);
        d_csrc[pos] = src;
    }
}

// ---------------- GCN GEMM: 64 rows x 128 cols per block, 8x4 microkernel ----------------
__global__ __launch_bounds__(256) void k_gemm128(const float* __restrict__ A,
                                                 const float* __restrict__ W) {
    __shared__ float sA[16][68];   // [k][row], padded
    __shared__ float sW[16][128];
    int tid = threadIdx.x;
    int tx = tid & 31;             // col group: cols tx*4
    int ty = tid >> 5;             // row group: rows ty*8
    int r0 = blockIdx.x * 64;

    float4 acc[8];
    #pragma unroll
    for (int r = 0; r < 8; r++) acc[r] = make_float4(0.f, 0.f, 0.f, 0.f);

    int lrow = tid >> 2, lkq = tid & 3;       // A-load role
    int wkk = tid >> 4, wc = (tid & 15) * 8;  // W-load role

    for (int kc = 0; kc < 128; kc += 16) {
        int grow = r0 + lrow;
        float4 av = make_float4(0.f, 0.f, 0.f, 0.f);
        if (grow < NN) av = *reinterpret_cast<const float4*>(&A[grow * AD + kc + lkq * 4]);
        sA[lkq * 4 + 0][lrow] = av.x;
        sA[lkq * 4 + 1][lrow] = av.y;
        sA[lkq * 4 + 2][lrow] = av.z;
        sA[lkq * 4 + 3][lrow] = av.w;
        *reinterpret_cast<float4*>(&sW[wkk][wc]) =
            *reinterpret_cast<const float4*>(&W[(kc + wkk) * AD + wc]);
        *reinterpret_cast<float4*>(&sW[wkk][wc + 4]) =
            *reinterpret_cast<const float4*>(&W[(kc + wkk) * AD + wc + 4]);
        __syncthreads();

        #pragma unroll
        for (int k2 = 0; k2 < 16; k2++) {
            float4 a0 = *reinterpret_cast<const float4*>(&sA[k2][ty * 8]);
            float4 a1 = *reinterpret_cast<const float4*>(&sA[k2][ty * 8 + 4]);
            float4 wv = *reinterpret_cast<const float4*>(&sW[k2][tx * 4]);
            acc[0].x += a0.x * wv.x; acc[0].y += a0.x * wv.y; acc[0].z += a0.x * wv.z; acc[0].w += a0.x * wv.w;
            acc[1].x += a0.y * wv.x; acc[1].y += a0.y * wv.y; acc[1].z += a0.y * wv.z; acc[1].w += a0.y * wv.w;
            acc[2].x += a0.z * wv.x; acc[2].y += a0.z * wv.y; acc[2].z += a0.z * wv.z; acc[2].w += a0.z * wv.w;
            acc[3].x += a0.w * wv.x; acc[3].y += a0.w * wv.y; acc[3].z += a0.w * wv.z; acc[3].w += a0.w * wv.w;
            acc[4].x += a1.x * wv.x; acc[4].y += a1.x * wv.y; acc[4].z += a1.x * wv.z; acc[4].w += a1.x * wv.w;
            acc[5].x += a1.y * wv.x; acc[5].y += a1.y * wv.y; acc[5].z += a1.y * wv.z; acc[5].w += a1.y * wv.w;
            acc[6].x += a1.z * wv.x; acc[6].y += a1.z * wv.y; acc[6].z += a1.z * wv.z; acc[6].w += a1.z * wv.w;
            acc[7].x += a1.w * wv.x; acc[7].y += a1.w * wv.y; acc[7].z += a1.w * wv.z; acc[7].w += a1.w * wv.w;
        }
        __syncthreads();
    }
    #pragma unroll
    for (int r = 0; r < 8; r++) {
        int row = r0 + ty * 8 + r;
        if (row < NN)
            *reinterpret_cast<float4*>(&d_h2[row * AD + tx * 4]) = acc[r];
    }
}

// warp per node: register-gather over in-edges + self loop, bias + gelu epilogue
__global__ void k_gcn_gather(const float* __restrict__ bias, float* __restrict__ out,
                             int apply_gelu) {
    int gid = blockIdx.x * blockDim.x + threadIdx.x;
    int n = gid >> 5;
    if (n >= NN) return;
    int lane = gid & 31;
    int beg = d_off[n], end = d_off[n + 1];
    float din = d_dinv[n];

    float4 acc = *reinterpret_cast<const float4*>(&d_h2[n * AD + lane * 4]);
    float sc = din * din;
    acc.x *= sc; acc.y *= sc; acc.z *= sc; acc.w *= sc;

    for (int e = beg; e < end; e++) {
        int src = d_csrc[e];                       // warp-uniform broadcast
        float nrm = din * d_dinv[src];
        float4 v = *reinterpret_cast<const float4*>(&d_h2[src * AD + lane * 4]);
        acc.x += nrm * v.x; acc.y += nrm * v.y; acc.z += nrm * v.z; acc.w += nrm * v.w;
    }
    float4 b = *reinterpret_cast<const float4*>(&bias[lane * 4]);
    acc.x += b.x; acc.y += b.y; acc.z += b.z; acc.w += b.w;
    if (apply_gelu) {
        acc.x = gelu_exact(acc.x); acc.y = gelu_exact(acc.y);
        acc.z = gelu_exact(acc.z); acc.w = gelu_exact(acc.w);
    }
    *reinterpret_cast<float4*>(&out[n * AD + lane * 4]) = acc;
}

// ---------------- GNA GEMM: 64 rows x 64 cols per block, 4x4 microkernel ----------------
__global__ __launch_bounds__(256) void k_gemm64(const float* __restrict__ A,
                                                const float* __restrict__ W,
                                                const float* __restrict__ bias,
                                                float* __restrict__ out,
                                                int final_mode) {
    __shared__ float sA[16][68];
    __shared__ float sW[16][64];
    int tid = threadIdx.x;
    int tx = tid & 15;             // cols tx*4
    int ty = tid >> 4;             // rows ty*4
    int r0 = blockIdx.x * 64;

    float4 acc[4];
    #pragma unroll
    for (int r = 0; r < 4; r++) acc[r] = make_float4(0.f, 0.f, 0.f, 0.f);

    int lrow = tid >> 2, lkq = tid & 3;
    int wkk = tid >> 4, wc = (tid & 15) * 4;

    for (int kc = 0; kc < 64; kc += 16) {
        int grow = r0 + lrow;
        float4 av = make_float4(0.f, 0.f, 0.f, 0.f);
        if (grow < NN) av = *reinterpret_cast<const float4*>(&A[grow * SD + kc + lkq * 4]);
        sA[lkq * 4 + 0][lrow] = av.x;
        sA[lkq * 4 + 1][lrow] = av.y;
        sA[lkq * 4 + 2][lrow] = av.z;
        sA[lkq * 4 + 3][lrow] = av.w;
        *reinterpret_cast<float4*>(&sW[wkk][wc]) =
            *reinterpret_cast<const float4*>(&W[(kc + wkk) * SD + wc]);
        __syncthreads();

        #pragma unroll
        for (int k2 = 0; k2 < 16; k2++) {
            float4 a0 = *reinterpret_cast<const float4*>(&sA[k2][ty * 4]);
            float4 wv = *reinterpret_cast<const float4*>(&sW[k2][tx * 4]);
            acc[0].x += a0.x * wv.x; acc[0].y += a0.x * wv.y; acc[0].z += a0.x * wv.z; acc[0].w += a0.x * wv.w;
            acc[1].x += a0.y * wv.x; acc[1].y += a0.y * wv.y; acc[1].z += a0.y * wv.z; acc[1].w += a0.y * wv.w;
            acc[2].x += a0.z * wv.x; acc[2].y += a0.z * wv.y; acc[2].z += a0.z * wv.z; acc[2].w += a0.z * wv.w;
            acc[3].x += a0.w * wv.x; acc[3].y += a0.w * wv.y; acc[3].z += a0.w * wv.z; acc[3].w += a0.w * wv.w;
        }
        __syncthreads();
    }
    float4 b = *reinterpret_cast<const float4*>(&bias[tx * 4]);
    #pragma unroll
    for (int r = 0; r < 4; r++) {
        int row = r0 + ty * 4 + r;
        if (row < NN) {
            float4 v = acc[r];
            v.x += b.x; v.y += b.y; v.z += b.z; v.w += b.w;
            if (final_mode) {
                float4 m = *reinterpret_cast<const float4*>(&d_msg[row * SD + tx * 4]);
                v.x = gelu_exact(v.x + m.x); v.y = gelu_exact(v.y + m.y);
                v.z = gelu_exact(v.z + m.z); v.w = gelu_exact(v.w + m.w);
            }
            *reinterpret_cast<float4*>(&out[row * SD + tx * 4]) = v;
        }
    }
}

// proj[n] = t[n] . a
__global__ void k_proj(const float* __restrict__ avec) {
    int n = blockIdx.x * blockDim.x + threadIdx.x;
    if (n >= NN) return;
    float p = 0.f;
    #pragma unroll
    for (int q = 0; q < 16; q++) {
        float4 tv = *reinterpret_cast<const float4*>(&d_t[n * SD + q * 4]);
        float4 av = *reinterpret_cast<const float4*>(&avec[q * 4]);
        p += tv.x * av.x + tv.y * av.y + tv.z * av.z + tv.w * av.w;
    }
    d_proj[n] = p;
}

// warp per node: full edge-softmax attention (max, exp, denom, msg), zero atomics
__global__ void k_gna_attn() {
    int gid = blockIdx.x * blockDim.x + threadIdx.x;
    int n = gid >> 5;
    if (n >= NN) return;
    int lane = gid & 31;
    int beg = d_off[n], end = d_off[n + 1];
    float projd = d_proj[n];

    // pass 1: amax (self loop alpha = 0)
    float amax = 0.f;
    for (int c = beg; c < end; c += 32) {
        int i = c + lane;
        if (i < end) {
            float a = projd - d_proj[d_csrc[i]];
            amax = fmaxf(amax, a);
        }
    }
    #pragma unroll
    for (int o = 16; o > 0; o >>= 1)
        amax = fmaxf(amax, __shfl_xor_sync(0xffffffffu, amax, o));

    // pass 2: exp-weighted accumulation (self term first)
    float es = expf(-amax);
    float2 tn = *reinterpret_cast<const float2*>(&d_t[n * SD + lane * 2]);
    float mx = es * tn.x, my = es * tn.y;
    float den = es;

    for (int c = beg; c < end; c += 32) {
        int i = c + lane;
        int cnt = min(32, end - c);
        int srcl = (i < end) ? d_csrc[i] : 0;
        float al = (i < end) ? (projd - d_proj[srcl]) : 0.f;
        float ewl = expf(al - amax);
        for (int j = 0; j < cnt; j++) {
            float ew = __shfl_sync(0xffffffffu, ewl, j);
            int sj = __shfl_sync(0xffffffffu, srcl, j);
            float2 tv = *reinterpret_cast<const float2*>(&d_t[sj * SD + lane * 2]);
            mx += ew * tv.x; my += ew * tv.y;
            den += ew;
        }
    }
    float inv = 1.f / (den + 1e-16f);
    float2 res = make_float2(mx * inv, my * inv);
    *reinterpret_cast<float2*>(&d_msg[n * SD + lane * 2]) = res;
}

// ---------------- host launcher ----------------
extern "C" void kernel_launch(void* const* d_in, const int* in_sizes, int n_in,
                              void* d_out, int out_size) {
    const float* x     = (const float*)d_in[0];
    const float* s     = (const float*)d_in[1];
    const int*   ei    = (const int*)d_in[2];
    const float* gcnW  = (const float*)d_in[3];
    const float* gcnb  = (const float*)d_in[4];
    const float* w1W   = (const float*)d_in[5];
    const float* w1b   = (const float*)d_in[6];
    const float* w2W   = (const float*)d_in[7];
    const float* w2b   = (const float*)d_in[8];
    const float* ga    = (const float*)d_in[9];
    float* out = (float*)d_out;

    void* p;
    cudaGetSymbolAddress(&p, d_deg);  int*   degp = (int*)p;
    cudaGetSymbolAddress(&p, d_off);  int*   offp = (int*)p;
    cudaGetSymbolAddress(&p, d_cur);  int*   curp = (int*)p;
    cudaGetSymbolAddress(&p, d_hbuf); float* hbufp = (float*)p;
    cudaGetSymbolAddress(&p, d_gbuf); float* gbufp = (float*)p;
    cudaGetSymbolAddress(&p, d_t);    float* tp   = (float*)p;

    // ---- CSR build (once) ----
    cudaMemsetAsync(degp, 0, NN * sizeof(int));
    k_deg_count<<<(NE + 255) / 256, 256>>>(ei);
    k_dinv<<<(NN + 255) / 256, 256>>>();
    k_scan<<<1, 1024>>>();
    cudaMemcpyAsync(curp, offp, NN * sizeof(int), cudaMemcpyDeviceToDevice);
    k_csr_scatter<<<(NE + 255) / 256, 256>>>(ei);

    const int GB = (NN + 63) / 64;          // gemm blocks
    const int WB = (NN * 32 + 255) / 256;   // warp-per-node blocks

    // ---- GCN stack ----
    const float* hin = x;
    for (int i = 0; i < NL; i++) {
        k_gemm128<<<GB, 256>>>(hin, gcnW + i * AD * AD);
        float* hout = (i == NL - 1) ? out : hbufp;
        k_gcn_gather<<<WB, 256>>>(gcnb + i * AD, hout, (i < NL - 1) ? 1 : 0);
        hin = hbufp;
    }

    // ---- GNA stack ----
    const float* gin = s;
    for (int i = 0; i < NL; i++) {
        k_gemm64<<<GB, 256>>>(gin, w2W + i * SD * SD, w2b + i * SD, tp, 0);
        k_proj<<<(NN + 255) / 256, 256>>>(ga + i * SD);
        k_gna_attn<<<WB, 256>>>();
        float* gout = (i == NL - 1) ? (out + NN * AD) : gbufp;
        k_gemm64<<<GB, 256>>>(gin, w1W + i * SD * SD, w1b + i * SD, gout, 1);
        gin = gbufp;
    }
}

// round 4
// speedup vs baseline: 2.6110x; 1.0641x over previous
#include <cuda_runtime.h>
#include <math.h>

#define NN 50000
#define NE 800000
#define AD 128
#define SD 64
#define NL 4

// ---------------- scratch (static device globals; no allocation) ----------------
__device__ float d_h2[NN * AD];     // GCN post-GEMM features, pre-scaled by dinv[row]
__device__ float d_hbuf[NN * AD];   // GCN inter-layer buffer
__device__ float d_t[NN * SD];      // GNA w2 output
__device__ float d_u[NN * SD];      // GNA w1 output (pre-attention)
__device__ float d_gbuf[NN * SD];   // GNA inter-layer buffer
__device__ float d_proj[NN];        // t . a
__device__ float d_dinv[NN];
__device__ int   d_deg[NN];
__device__ int   d_off[NN + 1];     // CSR offsets (dst-grouped)
__device__ int   d_cur[NN];
__device__ int   d_csrc[NE];        // CSR src per position

__device__ __forceinline__ float gelu_exact(float x) {
    return 0.5f * x * (1.0f + erff(x * 0.7071067811865476f));
}

// ---------------- degree / CSR build ----------------
__global__ void k_deg_count(const int* __restrict__ ei) {
    int i = blockIdx.x * blockDim.x + threadIdx.x;
    if (i < NE / 4) {
        int4 d4 = reinterpret_cast<const int4*>(ei + NE)[i];
        atomicAdd(&d_deg[d4.x], 1);
        atomicAdd(&d_deg[d4.y], 1);
        atomicAdd(&d_deg[d4.z], 1);
        atomicAdd(&d_deg[d4.w], 1);
    }
}

__global__ void k_dinv() {
    int n = blockIdx.x * blockDim.x + threadIdx.x;
    if (n < NN) d_dinv[n] = rsqrtf((float)(d_deg[n] + 1));
}

// single-block exclusive scan of d_deg into d_off (1024 threads)
__global__ void k_scan() {
    __shared__ int warpsums[32];
    int tid = threadIdx.x, lane = tid & 31, wid = tid >> 5;
    int carry = 0;
    if (tid == 0) d_off[0] = 0;
    for (int base = 0; base < NN; base += 1024) {
        int idx = base + tid;
        int v = (idx < NN) ? d_deg[idx] : 0;
        int x = v;
        #pragma unroll
        for (int o = 1; o < 32; o <<= 1) {
            int y = __shfl_up_sync(0xffffffffu, x, o);
            if (lane >= o) x += y;
        }
        if (lane == 31) warpsums[wid] = x;
        __syncthreads();
        if (wid == 0) {
            int w = warpsums[lane];
            #pragma unroll
            for (int o = 1; o < 32; o <<= 1) {
                int y = __shfl_up_sync(0xffffffffu, w, o);
                if (lane >= o) w += y;
            }
            warpsums[lane] = w;
        }
        __syncthreads();
        int prev = (wid > 0) ? warpsums[wid - 1] : 0;
        if (idx < NN) d_off[idx + 1] = carry + prev + x;
        int total = warpsums[31];
        __syncthreads();
        carry += total;
    }
}

__global__ void k_csr_scatter(const int* __restrict__ ei) {
    int i = blockIdx.x * blockDim.x + threadIdx.x;
    if (i < NE / 4) {
        int4 s4 = reinterpret_cast<const int4*>(ei)[i];
        int4 d4 = reinterpret_cast<const int4*>(ei + NE)[i];
        d_csrc[atomicAdd(&d_cur[d4.x], 1)] = s4.x;
        d_csrc[atomicAdd(&d_cur[d4.y], 1)] = s4.y;
        d_csrc[atomicAdd(&d_cur[d4.z], 1)] = s4.z;
        d_csrc[atomicAdd(&d_cur[d4.w], 1)] = s4.w;
    }
}

// ---------------- GCN GEMM: 64x128 tile, 8x4 microkernel; epilogue scales by dinv ----------------
__global__ __launch_bounds__(256) void k_gemm128(const float* __restrict__ A,
                                                 const float* __restrict__ W) {
    __shared__ float sA[16][68];   // [k][row], padded
    __shared__ float sW[16][128];
    int tid = threadIdx.x;
    int tx = tid & 31;             // cols tx*4
    int ty = tid >> 5;             // rows ty*8
    int r0 = blockIdx.x * 64;

    float4 acc[8];
    #pragma unroll
    for (int r = 0; r < 8; r++) acc[r] = make_float4(0.f, 0.f, 0.f, 0.f);

    int lrow = tid >> 2, lkq = tid & 3;
    int wkk = tid >> 4, wc = (tid & 15) * 8;

    for (int kc = 0; kc < 128; kc += 16) {
        int grow = r0 + lrow;
        float4 av = make_float4(0.f, 0.f, 0.f, 0.f);
        if (grow < NN) av = *reinterpret_cast<const float4*>(&A[grow * AD + kc + lkq * 4]);
        sA[lkq * 4 + 0][lrow] = av.x;
        sA[lkq * 4 + 1][lrow] = av.y;
        sA[lkq * 4 + 2][lrow] = av.z;
        sA[lkq * 4 + 3][lrow] = av.w;
        *reinterpret_cast<float4*>(&sW[wkk][wc]) =
            *reinterpret_cast<const float4*>(&W[(kc + wkk) * AD + wc]);
        *reinterpret_cast<float4*>(&sW[wkk][wc + 4]) =
            *reinterpret_cast<const float4*>(&W[(kc + wkk) * AD + wc + 4]);
        __syncthreads();

        #pragma unroll
        for (int k2 = 0; k2 < 16; k2++) {
            float4 a0 = *reinterpret_cast<const float4*>(&sA[k2][ty * 8]);
            float4 a1 = *reinterpret_cast<const float4*>(&sA[k2][ty * 8 + 4]);
            float4 wv = *reinterpret_cast<const float4*>(&sW[k2][tx * 4]);
            acc[0].x += a0.x * wv.x; acc[0].y += a0.x * wv.y; acc[0].z += a0.x * wv.z; acc[0].w += a0.x * wv.w;
            acc[1].x += a0.y * wv.x; acc[1].y += a0.y * wv.y; acc[1].z += a0.y * wv.z; acc[1].w += a0.y * wv.w;
            acc[2].x += a0.z * wv.x; acc[2].y += a0.z * wv.y; acc[2].z += a0.z * wv.z; acc[2].w += a0.z * wv.w;
            acc[3].x += a0.w * wv.x; acc[3].y += a0.w * wv.y; acc[3].z += a0.w * wv.z; acc[3].w += a0.w * wv.w;
            acc[4].x += a1.x * wv.x; acc[4].y += a1.x * wv.y; acc[4].z += a1.x * wv.z; acc[4].w += a1.x * wv.w;
            acc[5].x += a1.y * wv.x; acc[5].y += a1.y * wv.y; acc[5].z += a1.y * wv.z; acc[5].w += a1.y * wv.w;
            acc[6].x += a1.z * wv.x; acc[6].y += a1.z * wv.y; acc[6].z += a1.z * wv.z; acc[6].w += a1.z * wv.w;
            acc[7].x += a1.w * wv.x; acc[7].y += a1.w * wv.y; acc[7].z += a1.w * wv.z; acc[7].w += a1.w * wv.w;
        }
        __syncthreads();
    }
    #pragma unroll
    for (int r = 0; r < 8; r++) {
        int row = r0 + ty * 8 + r;
        if (row < NN) {
            float sc = d_dinv[row];   // pre-scale so gather needs no per-edge norm
            float4 v = acc[r];
            v.x *= sc; v.y *= sc; v.z *= sc; v.w *= sc;
            *reinterpret_cast<float4*>(&d_h2[row * AD + tx * 4]) = v;
        }
    }
}

// warp per node: acc = dinv[n] * (h2s[n] + sum h2s[src]) + b  (h2s already src-scaled)
__global__ void k_gcn_gather(const float* __restrict__ bias, float* __restrict__ out,
                             int apply_gelu) {
    int gid = blockIdx.x * blockDim.x + threadIdx.x;
    int n = gid >> 5;
    if (n >= NN) return;
    int lane = gid & 31;
    int beg = d_off[n], end = d_off[n + 1];
    float din = d_dinv[n];

    float4 acc = *reinterpret_cast<const float4*>(&d_h2[n * AD + lane * 4]);
    float4 acc2 = make_float4(0.f, 0.f, 0.f, 0.f);

    int e = beg;
    for (; e + 4 <= end; e += 4) {
        int s0 = d_csrc[e + 0];
        int s1 = d_csrc[e + 1];
        int s2 = d_csrc[e + 2];
        int s3 = d_csrc[e + 3];
        float4 v0 = *reinterpret_cast<const float4*>(&d_h2[s0 * AD + lane * 4]);
        float4 v1 = *reinterpret_cast<const float4*>(&d_h2[s1 * AD + lane * 4]);
        float4 v2 = *reinterpret_cast<const float4*>(&d_h2[s2 * AD + lane * 4]);
        float4 v3 = *reinterpret_cast<const float4*>(&d_h2[s3 * AD + lane * 4]);
        acc.x += v0.x; acc.y += v0.y; acc.z += v0.z; acc.w += v0.w;
        acc2.x += v1.x; acc2.y += v1.y; acc2.z += v1.z; acc2.w += v1.w;
        acc.x += v2.x; acc.y += v2.y; acc.z += v2.z; acc.w += v2.w;
        acc2.x += v3.x; acc2.y += v3.y; acc2.z += v3.z; acc2.w += v3.w;
    }
    for (; e < end; e++) {
        int s0 = d_csrc[e];
        float4 v0 = *reinterpret_cast<const float4*>(&d_h2[s0 * AD + lane * 4]);
        acc.x += v0.x; acc.y += v0.y; acc.z += v0.z; acc.w += v0.w;
    }
    acc.x += acc2.x; acc.y += acc2.y; acc.z += acc2.z; acc.w += acc2.w;

    float4 b = *reinterpret_cast<const float4*>(&bias[lane * 4]);
    acc.x = acc.x * din + b.x; acc.y = acc.y * din + b.y;
    acc.z = acc.z * din + b.z; acc.w = acc.w * din + b.w;
    if (apply_gelu) {
        acc.x = gelu_exact(acc.x); acc.y = gelu_exact(acc.y);
        acc.z = gelu_exact(acc.z); acc.w = gelu_exact(acc.w);
    }
    *reinterpret_cast<float4*>(&out[n * AD + lane * 4]) = acc;
}

// ---------------- GNA fused dual GEMM: t = A@W2+b2 (+proj=t.a), u = A@W1+b1 ----------------
__global__ __launch_bounds__(256) void k_gna_gemm(const float* __restrict__ A,
                                                  const float* __restrict__ W2,
                                                  const float* __restrict__ b2,
                                                  const float* __restrict__ W1,
                                                  const float* __restrict__ b1,
                                                  const float* __restrict__ avec) {
    __shared__ float sA[16][68];
    __shared__ float sW2[16][64];
    __shared__ float sW1[16][64];
    int tid = threadIdx.x;
    int tx = tid & 15;             // cols tx*4
    int ty = tid >> 4;             // rows ty*4
    int r0 = blockIdx.x * 64;

    float4 at[4], au[4];
    #pragma unroll
    for (int r = 0; r < 4; r++) {
        at[r] = make_float4(0.f, 0.f, 0.f, 0.f);
        au[r] = make_float4(0.f, 0.f, 0.f, 0.f);
    }

    int lrow = tid >> 2, lkq = tid & 3;
    int wkk = tid >> 4, wc = (tid & 15) * 4;

    for (int kc = 0; kc < 64; kc += 16) {
        int grow = r0 + lrow;
        float4 av = make_float4(0.f, 0.f, 0.f, 0.f);
        if (grow < NN) av = *reinterpret_cast<const float4*>(&A[grow * SD + kc + lkq * 4]);
        sA[lkq * 4 + 0][lrow] = av.x;
        sA[lkq * 4 + 1][lrow] = av.y;
        sA[lkq * 4 + 2][lrow] = av.z;
        sA[lkq * 4 + 3][lrow] = av.w;
        *reinterpret_cast<float4*>(&sW2[wkk][wc]) =
            *reinterpret_cast<const float4*>(&W2[(kc + wkk) * SD + wc]);
        *reinterpret_cast<float4*>(&sW1[wkk][wc]) =
            *reinterpret_cast<const float4*>(&W1[(kc + wkk) * SD + wc]);
        __syncthreads();

        #pragma unroll
        for (int k2 = 0; k2 < 16; k2++) {
            float4 a0 = *reinterpret_cast<const float4*>(&sA[k2][ty * 4]);
            float4 w2v = *reinterpret_cast<const float4*>(&sW2[k2][tx * 4]);
            float4 w1v = *reinterpret_cast<const float4*>(&sW1[k2][tx * 4]);
            at[0].x += a0.x * w2v.x; at[0].y += a0.x * w2v.y; at[0].z += a0.x * w2v.z; at[0].w += a0.x * w2v.w;
            at[1].x += a0.y * w2v.x; at[1].y += a0.y * w2v.y; at[1].z += a0.y * w2v.z; at[1].w += a0.y * w2v.w;
            at[2].x += a0.z * w2v.x; at[2].y += a0.z * w2v.y; at[2].z += a0.z * w2v.z; at[2].w += a0.z * w2v.w;
            at[3].x += a0.w * w2v.x; at[3].y += a0.w * w2v.y; at[3].z += a0.w * w2v.z; at[3].w += a0.w * w2v.w;
            au[0].x += a0.x * w1v.x; au[0].y += a0.x * w1v.y; au[0].z += a0.x * w1v.z; au[0].w += a0.x * w1v.w;
            au[1].x += a0.y * w1v.x; au[1].y += a0.y * w1v.y; au[1].z += a0.y * w1v.z; au[1].w += a0.y * w1v.w;
            au[2].x += a0.z * w1v.x; au[2].y += a0.z * w1v.y; au[2].z += a0.z * w1v.z; au[2].w += a0.z * w1v.w;
            au[3].x += a0.w * w1v.x; au[3].y += a0.w * w1v.y; au[3].z += a0.w * w1v.z; au[3].w += a0.w * w1v.w;
        }
        __syncthreads();
    }

    float4 bb2 = *reinterpret_cast<const float4*>(&b2[tx * 4]);
    float4 bb1 = *reinterpret_cast<const float4*>(&b1[tx * 4]);
    float4 av4 = *reinterpret_cast<const float4*>(&avec[tx * 4]);
    #pragma unroll
    for (int r = 0; r < 4; r++) {
        int row = r0 + ty * 4 + r;
        if (row >= NN) continue;
        float4 tv = at[r];
        tv.x += bb2.x; tv.y += bb2.y; tv.z += bb2.z; tv.w += bb2.w;
        *reinterpret_cast<float4*>(&d_t[row * SD + tx * 4]) = tv;
        // proj partial: dot over this thread's 4 cols, reduce across the 16 tx lanes
        float p = tv.x * av4.x + tv.y * av4.y + tv.z * av4.z + tv.w * av4.w;
        #pragma unroll
        for (int o = 1; o < 16; o <<= 1) p += __shfl_xor_sync(0xffffffffu, p, o);
        if (tx == 0) d_proj[row] = p;

        float4 uv = au[r];
        uv.x += bb1.x; uv.y += bb1.y; uv.z += bb1.z; uv.w += bb1.w;
        *reinterpret_cast<float4*>(&d_u[row * SD + tx * 4]) = uv;
    }
}

// warp per node: edge-softmax attention + epilogue out = gelu(u + msg/den)
__global__ void k_gna_attn(float* __restrict__ out) {
    int gid = blockIdx.x * blockDim.x + threadIdx.x;
    int n = gid >> 5;
    if (n >= NN) return;
    int lane = gid & 31;
    int beg = d_off[n], end = d_off[n + 1];
    float projd = d_proj[n];

    // pass 1: amax (self loop alpha = 0)
    float amax = 0.f;
    for (int c = beg; c < end; c += 32) {
        int i = c + lane;
        if (i < end) {
            float a = projd - d_proj[d_csrc[i]];
            amax = fmaxf(amax, a);
        }
    }
    #pragma unroll
    for (int o = 16; o > 0; o >>= 1)
        amax = fmaxf(amax, __shfl_xor_sync(0xffffffffu, amax, o));

    // pass 2: exp-weighted accumulation (self term first)
    float es = expf(-amax);
    float2 tn = *reinterpret_cast<const float2*>(&d_t[n * SD + lane * 2]);
    float mx = es * tn.x, my = es * tn.y;
    float den = es;

    for (int c = beg; c < end; c += 32) {
        int i = c + lane;
        int cnt = min(32, end - c);
        int srcl = (i < end) ? d_csrc[i] : 0;
        float al = (i < end) ? (projd - d_proj[srcl]) : 0.f;
        float ewl = expf(al - amax);
        for (int j = 0; j < cnt; j++) {
            float ew = __shfl_sync(0xffffffffu, ewl, j);
            int sj = __shfl_sync(0xffffffffu, srcl, j);
            float2 tv = *reinterpret_cast<const float2*>(&d_t[sj * SD + lane * 2]);
            mx += ew * tv.x; my += ew * tv.y;
            den += ew;
        }
    }
    float inv = 1.f / (den + 1e-16f);
    float2 uv = *reinterpret_cast<const float2*>(&d_u[n * SD + lane * 2]);
    float2 res;
    res.x = gelu_exact(uv.x + mx * inv);
    res.y = gelu_exact(uv.y + my * inv);
    *reinterpret_cast<float2*>(&out[n * SD + lane * 2]) = res;
}

// ---------------- host launcher ----------------
extern "C" void kernel_launch(void* const* d_in, const int* in_sizes, int n_in,
                              void* d_out, int out_size) {
    const float* x     = (const float*)d_in[0];
    const float* s     = (const float*)d_in[1];
    const int*   ei    = (const int*)d_in[2];
    const float* gcnW  = (const float*)d_in[3];
    const float* gcnb  = (const float*)d_in[4];
    const float* w1W   = (const float*)d_in[5];
    const float* w1b   = (const float*)d_in[6];
    const float* w2W   = (const float*)d_in[7];
    const float* w2b   = (const float*)d_in[8];
    const float* ga    = (const float*)d_in[9];
    float* out = (float*)d_out;

    void* p;
    cudaGetSymbolAddress(&p, d_deg);  int*   degp = (int*)p;
    cudaGetSymbolAddress(&p, d_off);  int*   offp = (int*)p;
    cudaGetSymbolAddress(&p, d_cur);  int*   curp = (int*)p;
    cudaGetSymbolAddress(&p, d_hbuf); float* hbufp = (float*)p;
    cudaGetSymbolAddress(&p, d_gbuf); float* gbufp = (float*)p;

    // ---- CSR build ----
    cudaMemsetAsync(degp, 0, NN * sizeof(int));
    k_deg_count<<<(NE / 4 + 255) / 256, 256>>>(ei);
    k_dinv<<<(NN + 255) / 256, 256>>>();
    k_scan<<<1, 1024>>>();
    cudaMemcpyAsync(curp, offp, NN * sizeof(int), cudaMemcpyDeviceToDevice);
    k_csr_scatter<<<(NE / 4 + 255) / 256, 256>>>(ei);

    const int GB = (NN + 63) / 64;
    const int WB = (NN * 32 + 255) / 256;

    // ---- GCN stack ----
    const float* hin = x;
    for (int i = 0; i < NL; i++) {
        k_gemm128<<<GB, 256>>>(hin, gcnW + i * AD * AD);
        float* hout = (i == NL - 1) ? out : hbufp;
        k_gcn_gather<<<WB, 256>>>(gcnb + i * AD, hout, (i < NL - 1) ? 1 : 0);
        hin = hbufp;
    }

    // ---- GNA stack ----
    const float* gin = s;
    for (int i = 0; i < NL; i++) {
        k_gna_gemm<<<GB, 256>>>(gin, w2W + i * SD * SD, w2b + i * SD,
                                w1W + i * SD * SD, w1b + i * SD, ga + i * SD);
        float* gout = (i == NL - 1) ? (out + NN * AD) : gbufp;
        k_gna_attn<<<WB, 256>>>(gout);
        gin = gbufp;
    }
}